// round 10
// baseline (speedup 1.0000x reference)
#include <cuda_runtime.h>
#include <cuda_bf16.h>
#include <stdint.h>
#include <stddef.h>

// ---------------------------------------------------------------------------
// SuperFrame: x[t,b,:] = src_tokens_flat[b*655360 + t*240 : +640]   (overlap!)
// y = x @ W^T + b ; out[t,b,o] = y[t,b,o] * sigmoid(y[t,b+16,o]), b in [0,16)
// out_lengths = src_lengths//3 - 2
//
// tf32 MMA path: cp.async fp32 tiles straight from the inputs (no staging),
// cvt.rna.tf32.f32 in-register (RN rounding — truncation would bias the
// 640-term dot by ~1e-3), mma.sync.m16n8k8.tf32, fp32 accumulate,
// fused thread-local GLU epilogue.
// ---------------------------------------------------------------------------

#define N_B   32
#define N_T   8192
#define N_F   80
#define T_OUT 2728              // (8192//3*3)/3 - 2
#define K_DIM 640
#define N_DIM 1024
#define BATCH_STRIDE 655360     // N_T*N_F elements

#define BM 128
#define BN 128
#define BK 32                   // 32 fp32 = 128 bytes per row
#define STAGES 3
#define A_STAGE_BYTES (BM*BK*4)           // 16384
#define B_STAGE_BYTES (BN*BK*4)           // 16384
#define SMEM_BYTES (STAGES*(A_STAGE_BYTES+B_STAGE_BYTES))  // 98304

#define NMAIN 44695552LL        // 2728*16*1024

// ---------------------------------------------------------------------------
// PTX helpers
// ---------------------------------------------------------------------------
__device__ __forceinline__ void cpasync16(uint32_t saddr, const void* gaddr) {
    asm volatile("cp.async.cg.shared.global [%0], [%1], 16;\n"
                 :: "r"(saddr), "l"(gaddr));
}
__device__ __forceinline__ void ldm4(uint32_t* r, uint32_t addr) {
    asm volatile("ldmatrix.sync.aligned.m8n8.x4.shared.b16 {%0,%1,%2,%3}, [%4];\n"
                 : "=r"(r[0]), "=r"(r[1]), "=r"(r[2]), "=r"(r[3]) : "r"(addr));
}
__device__ __forceinline__ void cvt_tf32(uint32_t& x) {
    asm volatile("cvt.rna.tf32.f32 %0, %0;\n" : "+r"(x));
}
__device__ __forceinline__ void mma1688_tf32(float* c, const uint32_t* a,
                                             uint32_t b0, uint32_t b1) {
    asm volatile(
        "mma.sync.aligned.m16n8k8.row.col.f32.tf32.tf32.f32 "
        "{%0,%1,%2,%3}, {%4,%5,%6,%7}, {%8,%9}, {%0,%1,%2,%3};\n"
        : "+f"(c[0]), "+f"(c[1]), "+f"(c[2]), "+f"(c[3])
        : "r"(a[0]), "r"(a[1]), "r"(a[2]), "r"(a[3]), "r"(b0), "r"(b1));
}

// ---------------------------------------------------------------------------
// Fused GEMM + GLU kernel.
// grid = (8 ntiles, 682 mtiles), 256 threads, 8 warps in 4(m) x 2(n).
// m = t*32 + b ; warp_m owns one full t-group of 32 batches ->
// GLU pair (b, b+16) lands in (m-tile 0, m-tile 1) of the SAME thread.
// ---------------------------------------------------------------------------
__global__ __launch_bounds__(256, 2)
void gemm_glu_kernel(const float* __restrict__ A, const float* __restrict__ Wm,
                     const float* __restrict__ bias, float* __restrict__ out) {
    extern __shared__ char smem_raw[];
    const uint32_t sbase = (uint32_t)__cvta_generic_to_shared(smem_raw);
    const int tid  = threadIdx.x;
    const int lane = tid & 31;
    const int wid  = tid >> 5;
    const int warp_m = wid >> 1;          // 0..3
    const int warp_n = wid & 1;           // 0..1
    const int ntile = blockIdx.x;         // 0..7
    const int mtile = blockIdx.y;         // 0..681
    const int m0 = mtile * BM;
    const int n0 = ntile * BN;

    // ---- cp.async offsets: 4 16B chunks per thread for each of A, B ----
    uint32_t ga[4], gb[4], sa[4];
    #pragma unroll
    for (int i = 0; i < 4; i++) {
        int c   = tid + i * 256;          // 0..1023
        int row = c >> 3;                 // 0..127
        int ch  = c & 7;                  // 16B chunk (4 fp32) within 128B row
        int m   = m0 + row;
        ga[i] = (uint32_t)((m & 31) * BATCH_STRIDE + (m >> 5) * 240 + ch * 4);
        gb[i] = (uint32_t)((n0 + row) * K_DIM + ch * 4);
        sa[i] = (uint32_t)(row * 128 + ((ch ^ (row & 7)) << 4));  // xor swizzle
    }

    auto issue = [&](int st, int ko) {    // ko in fp32 elements
        uint32_t aoff = sbase + st * A_STAGE_BYTES;
        uint32_t boff = sbase + STAGES * A_STAGE_BYTES + st * B_STAGE_BYTES;
        #pragma unroll
        for (int i = 0; i < 4; i++) {
            cpasync16(aoff + sa[i], A  + ga[i] + ko);
            cpasync16(boff + sa[i], Wm + gb[i] + ko);
        }
    };

    float acc[2][8][4] = {};

    // prologue: fill STAGES-1 stages
    issue(0, 0);
    asm volatile("cp.async.commit_group;\n");
    issue(1, BK);
    asm volatile("cp.async.commit_group;\n");

    const int KT = K_DIM / BK;            // 20
    for (int kt = 0; kt < KT; kt++) {
        int lkt = kt + STAGES - 1;
        if (lkt < KT) issue(lkt % STAGES, lkt * BK);
        asm volatile("cp.async.commit_group;\n");
        asm volatile("cp.async.wait_group 1;\n");
        __syncthreads();

        uint32_t sA = sbase + (kt % STAGES) * A_STAGE_BYTES;
        uint32_t sB = sbase + STAGES * A_STAGE_BYTES + (kt % STAGES) * B_STAGE_BYTES;

        #pragma unroll
        for (int s = 0; s < 4; s++) {     // 4 k8-steps per BK=32
            // A frags: x4 = {a0,a1,a2,a3} tiles (rows 0-7/8-15) x (k 0-3/4-7)
            uint32_t a[2][4];
            #pragma unroll
            for (int mi = 0; mi < 2; mi++) {
                int rl = warp_m * 32 + mi * 16 + (lane & 15);
                int ch = s * 2 + (lane >> 4);
                ldm4(a[mi], sA + rl * 128 + ((ch ^ (rl & 7)) << 4));
                cvt_tf32(a[mi][0]); cvt_tf32(a[mi][1]);
                cvt_tf32(a[mi][2]); cvt_tf32(a[mi][3]);
            }
            // B frags: each x4 covers two n8 frags: {b0,b1} x {n 0-7, 8-15}
            uint32_t bfr[4][4];
            #pragma unroll
            for (int g = 0; g < 4; g++) {
                int nl = warp_n * 64 + g * 16 + ((lane >> 4) << 3) + (lane & 7);
                int ch = s * 2 + ((lane >> 3) & 1);
                ldm4(bfr[g], sB + nl * 128 + ((ch ^ (nl & 7)) << 4));
                cvt_tf32(bfr[g][0]); cvt_tf32(bfr[g][1]);
                cvt_tf32(bfr[g][2]); cvt_tf32(bfr[g][3]);
            }
            #pragma unroll
            for (int mi = 0; mi < 2; mi++)
                #pragma unroll
                for (int nj = 0; nj < 8; nj++)
                    mma1688_tf32(acc[mi][nj], a[mi],
                                 bfr[nj >> 1][(nj & 1) * 2],
                                 bfr[nj >> 1][(nj & 1) * 2 + 1]);
        }
        __syncthreads();                  // protect stage reuse by next issue
    }

    // ---- fused GLU epilogue (thread-local (b, b+16) pairing) ----
    const int brow  = lane >> 2;          // 0..7
    const int col2  = (lane & 3) * 2;
    const int t_out = mtile * 4 + warp_m; // 0..2727
    #pragma unroll
    for (int nj = 0; nj < 8; nj++) {
        int o = n0 + warp_n * 64 + nj * 8 + col2;
        float bx = bias[o], by = bias[o + 1];
        // rows brow (b = brow) gated by m-tile 1 (b+16)
        float l0 = acc[0][nj][0] + bx, l1 = acc[0][nj][1] + by;
        float q0 = acc[1][nj][0] + bx, q1 = acc[1][nj][1] + by;
        float2 r0 = make_float2(l0 * (1.0f / (1.0f + expf(-q0))),
                                l1 * (1.0f / (1.0f + expf(-q1))));
        *reinterpret_cast<float2*>(out + ((size_t)t_out * 16 + brow) * 1024 + o) = r0;
        // rows brow+8
        float l2 = acc[0][nj][2] + bx, l3 = acc[0][nj][3] + by;
        float q2 = acc[1][nj][2] + bx, q3 = acc[1][nj][3] + by;
        float2 r1 = make_float2(l2 * (1.0f / (1.0f + expf(-q2))),
                                l3 * (1.0f / (1.0f + expf(-q3))));
        *reinterpret_cast<float2*>(out + ((size_t)t_out * 16 + brow + 8) * 1024 + o) = r1;
    }
}

// ---------------------------------------------------------------------------
// out_lengths tail. Sniffs int64 vs int32 src_lengths (int64 high word == 0
// since lengths <= 8192; a real int32 length is >= 3). Writes according to
// the space left after the main output.
// ---------------------------------------------------------------------------
__global__ void tail_kernel(const void* __restrict__ lens,
                            float* __restrict__ out, long long out_sz) {
    int i = threadIdx.x;
    if (i >= 32) return;
    long long rem = out_sz - NMAIN;
    const int* p32 = (const int*)lens;
    long long L = (p32[1] == 0) ? ((const long long*)lens)[i] : (long long)p32[i];
    long long v = L / 3 - 2;
    if (rem == 32) {
        out[NMAIN + i] = (float)v;                       // lengths as f32 values
    } else if (rem == 64) {
        ((long long*)(out + NMAIN))[i] = v;              // raw int64 layout
    }
}

// ---------------------------------------------------------------------------
extern "C" void kernel_launch(void* const* d_in, const int* in_sizes, int n_in,
                              void* d_out, int out_size) {
    const float* src  = (const float*)d_in[0];   // src_tokens (32,8192,80) f32
    const void*  lens = d_in[1];                 // src_lengths (i32 or i64)
    const float* W    = (const float*)d_in[2];   // (1024, 640) f32
    const float* bias = (const float*)d_in[3];   // (1024,) f32
    float* out = (float*)d_out;

    cudaFuncSetAttribute(gemm_glu_kernel,
                         cudaFuncAttributeMaxDynamicSharedMemorySize, SMEM_BYTES);

    dim3 grid(N_DIM / BN, (T_OUT * N_B) / BM);   // (8, 682)
    gemm_glu_kernel<<<grid, 256, SMEM_BYTES>>>(src, W, bias, out);

    tail_kernel<<<1, 32>>>(lens, out, (long long)out_size);
}

// round 11
// speedup vs baseline: 1.0001x; 1.0001x over previous
#include <cuda_runtime.h>
#include <cuda_bf16.h>
#include <stdint.h>
#include <stddef.h>

// ---------------------------------------------------------------------------
// SuperFrame: x[t,b,:] = src_tokens_flat[b*655360 + t*240 : +640]   (overlap!)
// y = x @ W^T + b ; out[t,b,o] = y[t,b,o] * sigmoid(y[t,b+16,o]), b in [0,16)
// out_lengths = src_lengths//3 - 2
//
// tf32 MMA path: cp.async fp32 tiles straight from the inputs (no staging),
// cvt.rna.tf32.f32 in-register (RN rounding — truncation would bias the
// 640-term dot by ~1e-3), mma.sync.m16n8k8.tf32, fp32 accumulate,
// fused thread-local GLU epilogue.
// ---------------------------------------------------------------------------

#define N_B   32
#define N_T   8192
#define N_F   80
#define T_OUT 2728              // (8192//3*3)/3 - 2
#define K_DIM 640
#define N_DIM 1024
#define BATCH_STRIDE 655360     // N_T*N_F elements

#define BM 128
#define BN 128
#define BK 32                   // 32 fp32 = 128 bytes per row
#define STAGES 3
#define A_STAGE_BYTES (BM*BK*4)           // 16384
#define B_STAGE_BYTES (BN*BK*4)           // 16384
#define SMEM_BYTES (STAGES*(A_STAGE_BYTES+B_STAGE_BYTES))  // 98304

#define NMAIN 44695552LL        // 2728*16*1024

// ---------------------------------------------------------------------------
// PTX helpers
// ---------------------------------------------------------------------------
__device__ __forceinline__ void cpasync16(uint32_t saddr, const void* gaddr) {
    asm volatile("cp.async.cg.shared.global [%0], [%1], 16;\n"
                 :: "r"(saddr), "l"(gaddr));
}
__device__ __forceinline__ void ldm4(uint32_t* r, uint32_t addr) {
    asm volatile("ldmatrix.sync.aligned.m8n8.x4.shared.b16 {%0,%1,%2,%3}, [%4];\n"
                 : "=r"(r[0]), "=r"(r[1]), "=r"(r[2]), "=r"(r[3]) : "r"(addr));
}
__device__ __forceinline__ void cvt_tf32(uint32_t& x) {
    asm volatile("cvt.rna.tf32.f32 %0, %0;\n" : "+r"(x));
}
__device__ __forceinline__ void mma1688_tf32(float* c, const uint32_t* a,
                                             uint32_t b0, uint32_t b1) {
    asm volatile(
        "mma.sync.aligned.m16n8k8.row.col.f32.tf32.tf32.f32 "
        "{%0,%1,%2,%3}, {%4,%5,%6,%7}, {%8,%9}, {%0,%1,%2,%3};\n"
        : "+f"(c[0]), "+f"(c[1]), "+f"(c[2]), "+f"(c[3])
        : "r"(a[0]), "r"(a[1]), "r"(a[2]), "r"(a[3]), "r"(b0), "r"(b1));
}

// ---------------------------------------------------------------------------
// Fused GEMM + GLU kernel.
// grid = (8 ntiles, 682 mtiles), 256 threads, 8 warps in 4(m) x 2(n).
// m = t*32 + b ; warp_m owns one full t-group of 32 batches ->
// GLU pair (b, b+16) lands in (m-tile 0, m-tile 1) of the SAME thread.
// ---------------------------------------------------------------------------
__global__ __launch_bounds__(256, 2)
void gemm_glu_kernel(const float* __restrict__ A, const float* __restrict__ Wm,
                     const float* __restrict__ bias, float* __restrict__ out) {
    extern __shared__ char smem_raw[];
    const uint32_t sbase = (uint32_t)__cvta_generic_to_shared(smem_raw);
    const int tid  = threadIdx.x;
    const int lane = tid & 31;
    const int wid  = tid >> 5;
    const int warp_m = wid >> 1;          // 0..3
    const int warp_n = wid & 1;           // 0..1
    const int ntile = blockIdx.x;         // 0..7
    const int mtile = blockIdx.y;         // 0..681
    const int m0 = mtile * BM;
    const int n0 = ntile * BN;

    // ---- cp.async offsets: 4 16B chunks per thread for each of A, B ----
    uint32_t ga[4], gb[4], sa[4];
    #pragma unroll
    for (int i = 0; i < 4; i++) {
        int c   = tid + i * 256;          // 0..1023
        int row = c >> 3;                 // 0..127
        int ch  = c & 7;                  // 16B chunk (4 fp32) within 128B row
        int m   = m0 + row;
        ga[i] = (uint32_t)((m & 31) * BATCH_STRIDE + (m >> 5) * 240 + ch * 4);
        gb[i] = (uint32_t)((n0 + row) * K_DIM + ch * 4);
        sa[i] = (uint32_t)(row * 128 + ((ch ^ (row & 7)) << 4));  // xor swizzle
    }

    auto issue = [&](int st, int ko) {    // ko in fp32 elements
        uint32_t aoff = sbase + st * A_STAGE_BYTES;
        uint32_t boff = sbase + STAGES * A_STAGE_BYTES + st * B_STAGE_BYTES;
        #pragma unroll
        for (int i = 0; i < 4; i++) {
            cpasync16(aoff + sa[i], A  + ga[i] + ko);
            cpasync16(boff + sa[i], Wm + gb[i] + ko);
        }
    };

    float acc[2][8][4] = {};

    // prologue: fill STAGES-1 stages
    issue(0, 0);
    asm volatile("cp.async.commit_group;\n");
    issue(1, BK);
    asm volatile("cp.async.commit_group;\n");

    const int KT = K_DIM / BK;            // 20
    for (int kt = 0; kt < KT; kt++) {
        int lkt = kt + STAGES - 1;
        if (lkt < KT) issue(lkt % STAGES, lkt * BK);
        asm volatile("cp.async.commit_group;\n");
        asm volatile("cp.async.wait_group 1;\n");
        __syncthreads();

        uint32_t sA = sbase + (kt % STAGES) * A_STAGE_BYTES;
        uint32_t sB = sbase + STAGES * A_STAGE_BYTES + (kt % STAGES) * B_STAGE_BYTES;

        #pragma unroll
        for (int s = 0; s < 4; s++) {     // 4 k8-steps per BK=32
            // A frags: x4 = {a0,a1,a2,a3} tiles (rows 0-7/8-15) x (k 0-3/4-7)
            uint32_t a[2][4];
            #pragma unroll
            for (int mi = 0; mi < 2; mi++) {
                int rl = warp_m * 32 + mi * 16 + (lane & 15);
                int ch = s * 2 + (lane >> 4);
                ldm4(a[mi], sA + rl * 128 + ((ch ^ (rl & 7)) << 4));
                cvt_tf32(a[mi][0]); cvt_tf32(a[mi][1]);
                cvt_tf32(a[mi][2]); cvt_tf32(a[mi][3]);
            }
            // B frags: each x4 covers two n8 frags: {b0,b1} x {n 0-7, 8-15}
            uint32_t bfr[4][4];
            #pragma unroll
            for (int g = 0; g < 4; g++) {
                int nl = warp_n * 64 + g * 16 + ((lane >> 4) << 3) + (lane & 7);
                int ch = s * 2 + ((lane >> 3) & 1);
                ldm4(bfr[g], sB + nl * 128 + ((ch ^ (nl & 7)) << 4));
                cvt_tf32(bfr[g][0]); cvt_tf32(bfr[g][1]);
                cvt_tf32(bfr[g][2]); cvt_tf32(bfr[g][3]);
            }
            #pragma unroll
            for (int mi = 0; mi < 2; mi++)
                #pragma unroll
                for (int nj = 0; nj < 8; nj++)
                    mma1688_tf32(acc[mi][nj], a[mi],
                                 bfr[nj >> 1][(nj & 1) * 2],
                                 bfr[nj >> 1][(nj & 1) * 2 + 1]);
        }
        __syncthreads();                  // protect stage reuse by next issue
    }

    // ---- fused GLU epilogue (thread-local (b, b+16) pairing) ----
    const int brow  = lane >> 2;          // 0..7
    const int col2  = (lane & 3) * 2;
    const int t_out = mtile * 4 + warp_m; // 0..2727
    #pragma unroll
    for (int nj = 0; nj < 8; nj++) {
        int o = n0 + warp_n * 64 + nj * 8 + col2;
        float bx = bias[o], by = bias[o + 1];
        // rows brow (b = brow) gated by m-tile 1 (b+16)
        float l0 = acc[0][nj][0] + bx, l1 = acc[0][nj][1] + by;
        float q0 = acc[1][nj][0] + bx, q1 = acc[1][nj][1] + by;
        float2 r0 = make_float2(l0 * (1.0f / (1.0f + expf(-q0))),
                                l1 * (1.0f / (1.0f + expf(-q1))));
        *reinterpret_cast<float2*>(out + ((size_t)t_out * 16 + brow) * 1024 + o) = r0;
        // rows brow+8
        float l2 = acc[0][nj][2] + bx, l3 = acc[0][nj][3] + by;
        float q2 = acc[1][nj][2] + bx, q3 = acc[1][nj][3] + by;
        float2 r1 = make_float2(l2 * (1.0f / (1.0f + expf(-q2))),
                                l3 * (1.0f / (1.0f + expf(-q3))));
        *reinterpret_cast<float2*>(out + ((size_t)t_out * 16 + brow + 8) * 1024 + o) = r1;
    }
}

// ---------------------------------------------------------------------------
// out_lengths tail. Sniffs int64 vs int32 src_lengths (int64 high word == 0
// since lengths <= 8192; a real int32 length is >= 3). Writes according to
// the space left after the main output.
// ---------------------------------------------------------------------------
__global__ void tail_kernel(const void* __restrict__ lens,
                            float* __restrict__ out, long long out_sz) {
    int i = threadIdx.x;
    if (i >= 32) return;
    long long rem = out_sz - NMAIN;
    const int* p32 = (const int*)lens;
    long long L = (p32[1] == 0) ? ((const long long*)lens)[i] : (long long)p32[i];
    long long v = L / 3 - 2;
    if (rem == 32) {
        out[NMAIN + i] = (float)v;                       // lengths as f32 values
    } else if (rem == 64) {
        ((long long*)(out + NMAIN))[i] = v;              // raw int64 layout
    }
}

// ---------------------------------------------------------------------------
extern "C" void kernel_launch(void* const* d_in, const int* in_sizes, int n_in,
                              void* d_out, int out_size) {
    const float* src  = (const float*)d_in[0];   // src_tokens (32,8192,80) f32
    const void*  lens = d_in[1];                 // src_lengths (i32 or i64)
    const float* W    = (const float*)d_in[2];   // (1024, 640) f32
    const float* bias = (const float*)d_in[3];   // (1024,) f32
    float* out = (float*)d_out;

    cudaFuncSetAttribute(gemm_glu_kernel,
                         cudaFuncAttributeMaxDynamicSharedMemorySize, SMEM_BYTES);

    dim3 grid(N_DIM / BN, (T_OUT * N_B) / BM);   // (8, 682)
    gemm_glu_kernel<<<grid, 256, SMEM_BYTES>>>(src, W, bias, out);

    tail_kernel<<<1, 32>>>(lens, out, (long long)out_size);
}

// round 13
// speedup vs baseline: 1.8877x; 1.8876x over previous
#include <cuda_runtime.h>
#include <cuda_fp16.h>
#include <stdint.h>
#include <stddef.h>

// ---------------------------------------------------------------------------
// SuperFrame: x[t,b,:] = src_flat[b*655360 + t*240 : +640]   (overlapping view)
// y = x @ W^T + b ; out[t,b,o] = y[t,b,o] * sigmoid(y[t,b+16,o]), b in [0,16)
// out_lengths = src_lengths//3 - 2
//
// fp16 mma.sync path (tcgen05 is rejected by the harness's compute_103 PTX
// target). fp16 has the same eps (2^-11, RN) as tf32 -> same ~3.1e-4 rel_err,
// but m16n8k16 shape = 2x K per tensor instruction vs tf32's k8.
// Structure identical to the proven R6/R11 kernel: 3-stage cp.async,
// xor-swizzled ldmatrix, fused thread-local GLU epilogue.
// ---------------------------------------------------------------------------

#define N_B   32
#define N_T   8192
#define N_F   80
#define T_OUT 2728              // (8192//3*3)/3 - 2
#define K_DIM 640
#define N_DIM 1024
#define BATCH_STRIDE 655360     // N_T*N_F elements

#define BM 128
#define BN 128
#define BK 64                   // 64 halfs = 128B per row
#define STAGES 3
#define A_STAGE_BYTES (BM*BK*2)           // 16384
#define B_STAGE_BYTES (BN*BK*2)           // 16384
#define SMEM_BYTES (STAGES*(A_STAGE_BYTES+B_STAGE_BYTES))  // 98304

#define NMAIN 44695552LL        // 2728*16*1024

// fp16 staging buffers (device globals: allocation-free scratch)
__device__ __half g_xh[(size_t)N_B*N_T*N_F];
__device__ __half g_wh[(size_t)N_DIM*K_DIM];

// ---------------------------------------------------------------------------
// fp32 -> fp16 (RN) conversion pre-kernels (grids sized exactly)
// ---------------------------------------------------------------------------
__global__ void cvt_x_kernel(const float* __restrict__ src) {
    int i = blockIdx.x * blockDim.x + threadIdx.x;       // float4 index
    float4 v = reinterpret_cast<const float4*>(src)[i];
    __half2 lo = __floats2half2_rn(v.x, v.y);
    __half2 hi = __floats2half2_rn(v.z, v.w);
    uint2 o;
    o.x = *reinterpret_cast<unsigned int*>(&lo);
    o.y = *reinterpret_cast<unsigned int*>(&hi);
    reinterpret_cast<uint2*>(g_xh)[i] = o;
}
__global__ void cvt_w_kernel(const float* __restrict__ src) {
    int i = blockIdx.x * blockDim.x + threadIdx.x;
    float4 v = reinterpret_cast<const float4*>(src)[i];
    __half2 lo = __floats2half2_rn(v.x, v.y);
    __half2 hi = __floats2half2_rn(v.z, v.w);
    uint2 o;
    o.x = *reinterpret_cast<unsigned int*>(&lo);
    o.y = *reinterpret_cast<unsigned int*>(&hi);
    reinterpret_cast<uint2*>(g_wh)[i] = o;
}

// ---------------------------------------------------------------------------
// PTX helpers
// ---------------------------------------------------------------------------
__device__ __forceinline__ void cpasync16(uint32_t saddr, const void* gaddr) {
    asm volatile("cp.async.cg.shared.global [%0], [%1], 16;\n"
                 :: "r"(saddr), "l"(gaddr));
}
__device__ __forceinline__ void ldm4(uint32_t* r, uint32_t addr) {
    asm volatile("ldmatrix.sync.aligned.m8n8.x4.shared.b16 {%0,%1,%2,%3}, [%4];\n"
                 : "=r"(r[0]), "=r"(r[1]), "=r"(r[2]), "=r"(r[3]) : "r"(addr));
}
__device__ __forceinline__ void mma16816(float* c, const uint32_t* a,
                                         uint32_t b0, uint32_t b1) {
    asm volatile(
        "mma.sync.aligned.m16n8k16.row.col.f32.f16.f16.f32 "
        "{%0,%1,%2,%3}, {%4,%5,%6,%7}, {%8,%9}, {%0,%1,%2,%3};\n"
        : "+f"(c[0]), "+f"(c[1]), "+f"(c[2]), "+f"(c[3])
        : "r"(a[0]), "r"(a[1]), "r"(a[2]), "r"(a[3]), "r"(b0), "r"(b1));
}

// ---------------------------------------------------------------------------
// Fused GEMM + GLU kernel.
// grid = (8 ntiles, 682 mtiles), 256 threads, 8 warps in 4(m) x 2(n).
// m = t*32 + b ; warp_m owns one full t-group of 32 batches ->
// GLU pair (b, b+16) is (m-tile 0, m-tile 1) of the SAME thread.
// ---------------------------------------------------------------------------
__global__ __launch_bounds__(256, 2)
void gemm_glu_kernel(const float* __restrict__ bias, float* __restrict__ out) {
    extern __shared__ char smem_raw[];
    const uint32_t sbase = (uint32_t)__cvta_generic_to_shared(smem_raw);
    const int tid  = threadIdx.x;
    const int lane = tid & 31;
    const int wid  = tid >> 5;
    const int warp_m = wid >> 1;          // 0..3
    const int warp_n = wid & 1;           // 0..1
    const int ntile = blockIdx.x;         // 0..7
    const int mtile = blockIdx.y;         // 0..681
    const int m0 = mtile * BM;
    const int n0 = ntile * BN;

    // ---- cp.async source/dest offsets (4 16B chunks/thread each) ----
    uint32_t ga[4], gb[4], sa[4];
    #pragma unroll
    for (int i = 0; i < 4; i++) {
        int c   = tid + i * 256;          // 0..1023
        int row = c >> 3;                 // 0..127
        int ch  = c & 7;                  // 16B chunk within 128B row
        int m   = m0 + row;
        ga[i] = (uint32_t)((m & 31) * BATCH_STRIDE + (m >> 5) * 240 + ch * 8);
        gb[i] = (uint32_t)((n0 + row) * K_DIM + ch * 8);
        sa[i] = (uint32_t)(row * 128 + ((ch ^ (row & 7)) << 4));  // xor swizzle
    }

    auto issue = [&](int st, int ko) {    // ko in half elements
        uint32_t aoff = sbase + st * A_STAGE_BYTES;
        uint32_t boff = sbase + STAGES * A_STAGE_BYTES + st * B_STAGE_BYTES;
        #pragma unroll
        for (int i = 0; i < 4; i++) {
            cpasync16(aoff + sa[i], g_xh + ga[i] + ko);
            cpasync16(boff + sa[i], g_wh + gb[i] + ko);
        }
    };

    float acc[2][8][4] = {};

    // prologue: fill STAGES-1 stages
    issue(0, 0);
    asm volatile("cp.async.commit_group;\n");
    issue(1, BK);
    asm volatile("cp.async.commit_group;\n");

    const int KT = K_DIM / BK;            // 10
    for (int kt = 0; kt < KT; kt++) {
        int lkt = kt + STAGES - 1;
        if (lkt < KT) issue(lkt % STAGES, lkt * BK);
        asm volatile("cp.async.commit_group;\n");
        asm volatile("cp.async.wait_group 1;\n");
        __syncthreads();

        uint32_t sA = sbase + (kt % STAGES) * A_STAGE_BYTES;
        uint32_t sB = sbase + STAGES * A_STAGE_BYTES + (kt % STAGES) * B_STAGE_BYTES;

        #pragma unroll
        for (int s = 0; s < 4; s++) {     // 4 k16-steps per BK=64
            uint32_t a[2][4];
            #pragma unroll
            for (int mi = 0; mi < 2; mi++) {
                int rl = warp_m * 32 + mi * 16 + (lane & 15);
                int ch = s * 2 + (lane >> 4);
                ldm4(a[mi], sA + rl * 128 + ((ch ^ (rl & 7)) << 4));
            }
            uint32_t bfr[4][4];
            #pragma unroll
            for (int g = 0; g < 4; g++) { // each x4 covers two n8 frags
                int nl = warp_n * 64 + g * 16 + ((lane >> 4) << 3) + (lane & 7);
                int ch = s * 2 + ((lane >> 3) & 1);
                ldm4(bfr[g], sB + nl * 128 + ((ch ^ (nl & 7)) << 4));
            }
            #pragma unroll
            for (int mi = 0; mi < 2; mi++)
                #pragma unroll
                for (int nj = 0; nj < 8; nj++)
                    mma16816(acc[mi][nj], a[mi],
                             bfr[nj >> 1][(nj & 1) * 2],
                             bfr[nj >> 1][(nj & 1) * 2 + 1]);
        }
        __syncthreads();                  // protect stage reuse by next issue
    }

    // ---- fused GLU epilogue (thread-local (b, b+16) pairing) ----
    const int brow  = lane >> 2;          // 0..7
    const int col2  = (lane & 3) * 2;
    const int t_out = mtile * 4 + warp_m; // 0..2727
    #pragma unroll
    for (int nj = 0; nj < 8; nj++) {
        int o = n0 + warp_n * 64 + nj * 8 + col2;
        float bx = bias[o], by = bias[o + 1];
        // rows brow (b = brow) gated by m-tile 1 (b+16)
        float l0 = acc[0][nj][0] + bx, l1 = acc[0][nj][1] + by;
        float q0 = acc[1][nj][0] + bx, q1 = acc[1][nj][1] + by;
        float2 r0 = make_float2(l0 * (1.0f / (1.0f + expf(-q0))),
                                l1 * (1.0f / (1.0f + expf(-q1))));
        *reinterpret_cast<float2*>(out + ((size_t)t_out * 16 + brow) * 1024 + o) = r0;
        // rows brow+8
        float l2 = acc[0][nj][2] + bx, l3 = acc[0][nj][3] + by;
        float q2 = acc[1][nj][2] + bx, q3 = acc[1][nj][3] + by;
        float2 r1 = make_float2(l2 * (1.0f / (1.0f + expf(-q2))),
                                l3 * (1.0f / (1.0f + expf(-q3))));
        *reinterpret_cast<float2*>(out + ((size_t)t_out * 16 + brow + 8) * 1024 + o) = r1;
    }
}

// ---------------------------------------------------------------------------
// out_lengths tail (proven). Sniffs i64 vs i32 lengths via zero high word.
// ---------------------------------------------------------------------------
__global__ void tail_kernel(const void* __restrict__ lens,
                            float* __restrict__ out, long long out_sz) {
    int i = threadIdx.x;
    if (i >= 32) return;
    long long rem = out_sz - NMAIN;
    const int* p32 = (const int*)lens;
    long long L = (p32[1] == 0) ? ((const long long*)lens)[i] : (long long)p32[i];
    long long v = L / 3 - 2;
    if (rem == 32) {
        out[NMAIN + i] = (float)v;                       // lengths as f32 values
    } else if (rem == 64) {
        ((long long*)(out + NMAIN))[i] = v;              // raw int64 layout
    }
}

// ---------------------------------------------------------------------------
extern "C" void kernel_launch(void* const* d_in, const int* in_sizes, int n_in,
                              void* d_out, int out_size) {
    const float* src  = (const float*)d_in[0];   // src_tokens (32,8192,80) f32
    const void*  lens = d_in[1];                 // src_lengths (i32 or i64)
    const float* W    = (const float*)d_in[2];   // (1024, 640) f32
    const float* bias = (const float*)d_in[3];   // (1024,) f32
    float* out = (float*)d_out;

    cudaFuncSetAttribute(gemm_glu_kernel,
                         cudaFuncAttributeMaxDynamicSharedMemorySize, SMEM_BYTES);

    cvt_x_kernel<<<(N_B * N_T * N_F / 4) / 256, 256>>>(src);   // 20480 blocks
    cvt_w_kernel<<<(N_DIM * K_DIM / 4) / 256, 256>>>(W);       // 640 blocks

    dim3 grid(N_DIM / BN, (T_OUT * N_B) / BM);   // (8, 682)
    gemm_glu_kernel<<<grid, 256, SMEM_BYTES>>>(bias, out);

    tail_kernel<<<1, 32>>>(lens, out, (long long)out_size);
}

// round 14
// speedup vs baseline: 1.9492x; 1.0326x over previous
#include <cuda_runtime.h>
#include <cuda_fp16.h>
#include <stdint.h>
#include <stddef.h>

// ---------------------------------------------------------------------------
// SuperFrame: x[t,b,:] = src_flat[b*655360 + t*240 : +640]   (overlapping view)
// y = x @ W^T + b ; out[t,b,o] = y[t,b,o] * sigmoid(y[t,b+16,o]), b in [0,16)
// out_lengths = src_lengths//3 - 2
//
// fp16 mma.sync m16n8k16 (fp32 acc) — same eps as tf32 (2^-11 RN) => 3.1e-4.
// R13 structure + (a) single __syncthreads per k-tile (restructured cp.async
// pipeline), (b) one fused prep kernel (cvt_x + cvt_w + tail) so the whole
// call is 2 launches (also puts the GEMM under ncu's -s 5 window).
// ---------------------------------------------------------------------------

#define N_B   32
#define N_T   8192
#define N_F   80
#define T_OUT 2728              // (8192//3*3)/3 - 2
#define K_DIM 640
#define N_DIM 1024
#define BATCH_STRIDE 655360     // N_T*N_F elements

#define BM 128
#define BN 128
#define BK 64                   // 64 halfs = 128B per row
#define STAGES 3
#define A_STAGE_BYTES (BM*BK*2)           // 16384
#define B_STAGE_BYTES (BN*BK*2)           // 16384
#define SMEM_BYTES (STAGES*(A_STAGE_BYTES+B_STAGE_BYTES))  // 98304

#define NMAIN 44695552LL        // 2728*16*1024

// fp16 staging buffers (device globals: allocation-free scratch)
__device__ __half g_xh[(size_t)N_B*N_T*N_F];
__device__ __half g_wh[(size_t)N_DIM*K_DIM];

// ---------------------------------------------------------------------------
// Fused prep: blocks [0,20480) cvt x, [20480,21120) cvt w, block 21120 tail.
// ---------------------------------------------------------------------------
#define XBLK 20480              // 32*8192*80 / (256*4)
#define WBLK 640                // 1024*640  / (256*4)

__global__ void prep_kernel(const float* __restrict__ src,
                            const float* __restrict__ W,
                            const void* __restrict__ lens,
                            float* __restrict__ out, long long out_sz) {
    int b = blockIdx.x;
    if (b < XBLK) {
        int i = b * 256 + threadIdx.x;               // float4 index
        float4 v = reinterpret_cast<const float4*>(src)[i];
        __half2 lo = __floats2half2_rn(v.x, v.y);
        __half2 hi = __floats2half2_rn(v.z, v.w);
        uint2 o;
        o.x = *reinterpret_cast<unsigned int*>(&lo);
        o.y = *reinterpret_cast<unsigned int*>(&hi);
        reinterpret_cast<uint2*>(g_xh)[i] = o;
    } else if (b < XBLK + WBLK) {
        int i = (b - XBLK) * 256 + threadIdx.x;
        float4 v = reinterpret_cast<const float4*>(W)[i];
        __half2 lo = __floats2half2_rn(v.x, v.y);
        __half2 hi = __floats2half2_rn(v.z, v.w);
        uint2 o;
        o.x = *reinterpret_cast<unsigned int*>(&lo);
        o.y = *reinterpret_cast<unsigned int*>(&hi);
        reinterpret_cast<uint2*>(g_wh)[i] = o;
    } else {
        int i = threadIdx.x;
        if (i >= 32) return;
        long long rem = out_sz - NMAIN;
        const int* p32 = (const int*)lens;
        long long L = (p32[1] == 0) ? ((const long long*)lens)[i]
                                    : (long long)p32[i];
        long long v = L / 3 - 2;
        if (rem == 32) {
            out[NMAIN + i] = (float)v;               // lengths as f32 values
        } else if (rem == 64) {
            ((long long*)(out + NMAIN))[i] = v;      // raw int64 layout
        }
    }
}

// ---------------------------------------------------------------------------
// PTX helpers
// ---------------------------------------------------------------------------
__device__ __forceinline__ void cpasync16(uint32_t saddr, const void* gaddr) {
    asm volatile("cp.async.cg.shared.global [%0], [%1], 16;\n"
                 :: "r"(saddr), "l"(gaddr));
}
__device__ __forceinline__ void ldm4(uint32_t* r, uint32_t addr) {
    asm volatile("ldmatrix.sync.aligned.m8n8.x4.shared.b16 {%0,%1,%2,%3}, [%4];\n"
                 : "=r"(r[0]), "=r"(r[1]), "=r"(r[2]), "=r"(r[3]) : "r"(addr));
}
__device__ __forceinline__ void mma16816(float* c, const uint32_t* a,
                                         uint32_t b0, uint32_t b1) {
    asm volatile(
        "mma.sync.aligned.m16n8k16.row.col.f32.f16.f16.f32 "
        "{%0,%1,%2,%3}, {%4,%5,%6,%7}, {%8,%9}, {%0,%1,%2,%3};\n"
        : "+f"(c[0]), "+f"(c[1]), "+f"(c[2]), "+f"(c[3])
        : "r"(a[0]), "r"(a[1]), "r"(a[2]), "r"(a[3]), "r"(b0), "r"(b1));
}

// ---------------------------------------------------------------------------
// Fused GEMM + GLU kernel.
// grid = (8 ntiles, 682 mtiles), 256 threads, 8 warps in 4(m) x 2(n).
// m = t*32 + b ; warp_m owns one full t-group of 32 batches ->
// GLU pair (b, b+16) is (m-tile 0, m-tile 1) of the SAME thread.
// Pipeline: wait_group 1 -> barrier -> issue(kt+2) -> mma(kt).
// The single barrier orders (i) stage-kt cp.async writes before all reads,
// and (ii) stage-(kt-1) reads before stage-(kt+2)%3==(kt-1)%3 overwrites.
// ---------------------------------------------------------------------------
__global__ __launch_bounds__(256, 2)
void gemm_glu_kernel(const float* __restrict__ bias, float* __restrict__ out) {
    extern __shared__ char smem_raw[];
    const uint32_t sbase = (uint32_t)__cvta_generic_to_shared(smem_raw);
    const int tid  = threadIdx.x;
    const int lane = tid & 31;
    const int wid  = tid >> 5;
    const int warp_m = wid >> 1;          // 0..3
    const int warp_n = wid & 1;           // 0..1
    const int ntile = blockIdx.x;         // 0..7
    const int mtile = blockIdx.y;         // 0..681
    const int m0 = mtile * BM;
    const int n0 = ntile * BN;

    // ---- cp.async source/dest offsets (4 16B chunks/thread each) ----
    uint32_t ga[4], gb[4], sa[4];
    #pragma unroll
    for (int i = 0; i < 4; i++) {
        int c   = tid + i * 256;          // 0..1023
        int row = c >> 3;                 // 0..127
        int ch  = c & 7;                  // 16B chunk within 128B row
        int m   = m0 + row;
        ga[i] = (uint32_t)((m & 31) * BATCH_STRIDE + (m >> 5) * 240 + ch * 8);
        gb[i] = (uint32_t)((n0 + row) * K_DIM + ch * 8);
        sa[i] = (uint32_t)(row * 128 + ((ch ^ (row & 7)) << 4));  // xor swizzle
    }

    auto issue = [&](int st, int ko) {    // ko in half elements
        uint32_t aoff = sbase + st * A_STAGE_BYTES;
        uint32_t boff = sbase + STAGES * A_STAGE_BYTES + st * B_STAGE_BYTES;
        #pragma unroll
        for (int i = 0; i < 4; i++) {
            cpasync16(aoff + sa[i], g_xh + ga[i] + ko);
            cpasync16(boff + sa[i], g_wh + gb[i] + ko);
        }
    };

    float acc[2][8][4] = {};

    // prologue: fill first 2 stages
    issue(0, 0);
    asm volatile("cp.async.commit_group;\n");
    issue(1, BK);
    asm volatile("cp.async.commit_group;\n");

    const int KT = K_DIM / BK;            // 10
    for (int kt = 0; kt < KT; kt++) {
        asm volatile("cp.async.wait_group 1;\n");   // stage kt complete
        __syncthreads();
        if (kt + 2 < KT) issue((kt + 2) % STAGES, (kt + 2) * BK);
        asm volatile("cp.async.commit_group;\n");   // unconditional: keeps order

        uint32_t sA = sbase + (kt % STAGES) * A_STAGE_BYTES;
        uint32_t sB = sbase + STAGES * A_STAGE_BYTES + (kt % STAGES) * B_STAGE_BYTES;

        #pragma unroll
        for (int s = 0; s < 4; s++) {     // 4 k16-steps per BK=64
            uint32_t a[2][4];
            #pragma unroll
            for (int mi = 0; mi < 2; mi++) {
                int rl = warp_m * 32 + mi * 16 + (lane & 15);
                int ch = s * 2 + (lane >> 4);
                ldm4(a[mi], sA + rl * 128 + ((ch ^ (rl & 7)) << 4));
            }
            uint32_t bfr[4][4];
            #pragma unroll
            for (int g = 0; g < 4; g++) { // each x4 covers two n8 frags
                int nl = warp_n * 64 + g * 16 + ((lane >> 4) << 3) + (lane & 7);
                int ch = s * 2 + ((lane >> 3) & 1);
                ldm4(bfr[g], sB + nl * 128 + ((ch ^ (nl & 7)) << 4));
            }
            #pragma unroll
            for (int mi = 0; mi < 2; mi++)
                #pragma unroll
                for (int nj = 0; nj < 8; nj++)
                    mma16816(acc[mi][nj], a[mi],
                             bfr[nj >> 1][(nj & 1) * 2],
                             bfr[nj >> 1][(nj & 1) * 2 + 1]);
        }
    }

    // ---- fused GLU epilogue (thread-local (b, b+16) pairing) ----
    const int brow  = lane >> 2;          // 0..7
    const int col2  = (lane & 3) * 2;
    const int t_out = mtile * 4 + warp_m; // 0..2727
    #pragma unroll
    for (int nj = 0; nj < 8; nj++) {
        int o = n0 + warp_n * 64 + nj * 8 + col2;
        float bx = bias[o], by = bias[o + 1];
        // rows brow (b = brow) gated by m-tile 1 (b+16)
        float l0 = acc[0][nj][0] + bx, l1 = acc[0][nj][1] + by;
        float q0 = acc[1][nj][0] + bx, q1 = acc[1][nj][1] + by;
        float2 r0 = make_float2(l0 * (1.0f / (1.0f + expf(-q0))),
                                l1 * (1.0f / (1.0f + expf(-q1))));
        *reinterpret_cast<float2*>(out + ((size_t)t_out * 16 + brow) * 1024 + o) = r0;
        // rows brow+8
        float l2 = acc[0][nj][2] + bx, l3 = acc[0][nj][3] + by;
        float q2 = acc[1][nj][2] + bx, q3 = acc[1][nj][3] + by;
        float2 r1 = make_float2(l2 * (1.0f / (1.0f + expf(-q2))),
                                l3 * (1.0f / (1.0f + expf(-q3))));
        *reinterpret_cast<float2*>(out + ((size_t)t_out * 16 + brow + 8) * 1024 + o) = r1;
    }
}

// ---------------------------------------------------------------------------
extern "C" void kernel_launch(void* const* d_in, const int* in_sizes, int n_in,
                              void* d_out, int out_size) {
    const float* src  = (const float*)d_in[0];   // src_tokens (32,8192,80) f32
    const void*  lens = d_in[1];                 // src_lengths (i32 or i64)
    const float* W    = (const float*)d_in[2];   // (1024, 640) f32
    const float* bias = (const float*)d_in[3];   // (1024,) f32
    float* out = (float*)d_out;

    cudaFuncSetAttribute(gemm_glu_kernel,
                         cudaFuncAttributeMaxDynamicSharedMemorySize, SMEM_BYTES);

    prep_kernel<<<XBLK + WBLK + 1, 256>>>(src, W, lens, out,
                                          (long long)out_size);

    dim3 grid(N_DIM / BN, (T_OUT * N_B) / BM);   // (8, 682)
    gemm_glu_kernel<<<grid, 256, SMEM_BYTES>>>(bias, out);
}